// round 16
// baseline (speedup 1.0000x reference)
#include <cuda_runtime.h>
#include <math.h>

// SPD log-map: Chebyshev deg-8 + Paterson-Stockmeyer, base W = T_3.
//   S = (P0 - P2) + W*(P1 + 2*W*P2),  P_q = cf[q][0] I + cf[q][1] X~ + cf[q][2] T2
// 4 matmuls: X*X (-> bound + T2 elementwise), W=T3, W*P2, W*b1.
// 8x4 register tiles over the upper triangle (72 tiles, 96 threads);
// A-operand rows read as contiguous float4 via symmetry (A[i][k]=A[k][i]).
// TWO smem matrix buffers; E0 = P0-P2 is PRE-STORED into the output buffer at
// matmul-2 time and read back (same thread, same positions) at matmul-4 --
// this frees 32 persistent registers so the kernel fits the 113-reg cap of
// 6 CTAs/SM (18 warps) WITHOUT spills (the R13 failure mode).
// Inner product: packed fp32 FMA (fma.rn.f32x2), broadcast-B scheme
// (validated fastest). Per k-step: 3 LDS + 4 bcast + 16 FFMA2. Full fp32.
// Eigen bound: lammax <= sqrt(gersh(X^2)) (always valid, tighter here).

#define LDM      68
#define NTHREADS 96
#define NTILES   72
#define MATN     64
#define MATSZ    (MATN * MATN)
#define OUTSZ    2080

typedef unsigned long long u64;

__device__ __forceinline__ void fma2(u64& d, u64 a, u64 b) {
    asm("fma.rn.f32x2 %0, %1, %2, %0;" : "+l"(d) : "l"(a), "l"(b));
}
__device__ __forceinline__ u64 bcast2(float x) {
    u64 r; asm("mov.b64 %0, {%1, %1};" : "=l"(r) : "f"(x)); return r;
}

__device__ __forceinline__ void mm_tile8(const float* __restrict__ A,
                                         const float* __restrict__ B,
                                         int i0, int j0, float s[8][4])
{
    u64 acc[4][4];
    #pragma unroll
    for (int p = 0; p < 4; p++)
        #pragma unroll
        for (int c = 0; c < 4; c++) acc[p][c] = 0ull;
    const float* Ap = A + i0;
    const float* Bp = B + j0;
    #pragma unroll 4
    for (int kk = 0; kk < MATN; kk++) {
        // A[i0..i0+7][kk] == A-row kk (symmetry) -> two 16B loads, pairs prepacked
        const ulonglong2 a0 = *(const ulonglong2*)(Ap + kk * LDM);      // rows (0,1),(2,3)
        const ulonglong2 a1 = *(const ulonglong2*)(Ap + kk * LDM + 4);  // rows (4,5),(6,7)
        const float4 bv = *(const float4*)(Bp + kk * LDM);
        const u64 pb0 = bcast2(bv.x), pb1 = bcast2(bv.y);
        const u64 pb2 = bcast2(bv.z), pb3 = bcast2(bv.w);
        const u64 pa[4] = {a0.x, a0.y, a1.x, a1.y};
        #pragma unroll
        for (int p = 0; p < 4; p++) {
            fma2(acc[p][0], pa[p], pb0);
            fma2(acc[p][1], pa[p], pb1);
            fma2(acc[p][2], pa[p], pb2);
            fma2(acc[p][3], pa[p], pb3);
        }
    }
    #pragma unroll
    for (int p = 0; p < 4; p++)
        #pragma unroll
        for (int c = 0; c < 4; c++) {
            float lo, hi;
            asm("mov.b64 {%0, %1}, %2;" : "=f"(lo), "=f"(hi) : "l"(acc[p][c]));
            s[2 * p][c] = lo;
            s[2 * p + 1][c] = hi;
        }
}

__device__ __forceinline__ void load_tile8(const float* __restrict__ M,
                                           int i0, int j0, float v[8][4])
{
    #pragma unroll
    for (int r = 0; r < 8; r++) {
        const float4 t = *(const float4*)(M + (i0 + r) * LDM + j0);
        v[r][0] = t.x; v[r][1] = t.y; v[r][2] = t.z; v[r][3] = t.w;
    }
}

__device__ __forceinline__ void store_tile8_sym(float* __restrict__ M,
                                                int i0, int j0, bool straddle,
                                                const float v[8][4])
{
    if (!straddle) {
        #pragma unroll
        for (int r = 0; r < 8; r++)
            *(float4*)(M + (i0 + r) * LDM + j0) =
                make_float4(v[r][0], v[r][1], v[r][2], v[r][3]);
        #pragma unroll
        for (int c = 0; c < 4; c++) {
            *(float4*)(M + (j0 + c) * LDM + i0) =
                make_float4(v[0][c], v[1][c], v[2][c], v[3][c]);
            *(float4*)(M + (j0 + c) * LDM + i0 + 4) =
                make_float4(v[4][c], v[5][c], v[6][c], v[7][c]);
        }
    } else {
        #pragma unroll
        for (int r = 0; r < 8; r++)
            #pragma unroll
            for (int c = 0; c < 4; c++) {
                const int i = i0 + r, j = j0 + c;
                if (i <= j) {
                    M[i * LDM + j] = v[r][c];
                    if (i < j) M[j * LDM + i] = v[r][c];
                }
            }
    }
}

__global__ void __launch_bounds__(NTHREADS, 6)
spd_log_cheb_e0g_kernel(const float* __restrict__ xg, float* __restrict__ outg)
{
    extern __shared__ float sm[];
    float* Xs  = sm + 0 * MATN * LDM;   // X -> X~ -> W
    float* T2s = sm + 1 * MATN * LDM;   // X^2 -> T2 -> P2 -> b1
    float* rs  = sm + 2 * MATN * LDM;   // 64 rowsums + 1 max

    const int t = threadIdx.x;
    const float* X = xg + (size_t)blockIdx.x * MATSZ;
    float* o = outg + (size_t)blockIdx.x * OUTSZ;

    // ---- load X ----
    for (int e = t; e < MATSZ; e += NTHREADS)
        Xs[(e >> 6) * LDM + (e & 63)] = X[e];
    __syncthreads();

    // ---- tile assignment: t < 72 owns 8x4 tile (bi, bj), bj >= 2*bi ----
    const bool active = (t < NTILES);
    int bi = 0, bj = 0;
    {
        int tt = active ? t : 0;
        while (tt >= 16 - 2 * bi) { tt -= 16 - 2 * bi; bi++; }
        bj = 2 * bi + tt;
    }
    const int i0 = bi * 8, j0 = bj * 4;
    const bool straddle = (bj <= 2 * bi + 1);

    // ---- matmul 1: X2 = X * X -> T2s ----
    if (active) {
        float s[8][4];
        mm_tile8(Xs, Xs, i0, j0, s);
        store_tile8_sym(T2s, i0, j0, straddle, s);
    }
    __syncthreads();

    // ---- Gershgorin bound on X^2 (lammax <= sqrt(gersh(X^2))) ----
    if (t < MATN) {
        float sb = 0.f;
        #pragma unroll
        for (int j = 0; j < MATN; j += 4) {
            const float4 xb = *(const float4*)(T2s + t * LDM + j);
            sb += fabsf(xb.x) + fabsf(xb.y) + fabsf(xb.z) + fabsf(xb.w);
        }
        rs[t] = sb;
    }
    __syncthreads();
    if (t < 32) {
        float mb = fmaxf(rs[t], rs[t + 32]);
        #pragma unroll
        for (int o2 = 16; o2 > 0; o2 >>= 1)
            mb = fmaxf(mb, __shfl_xor_sync(0xffffffffu, mb, o2));
        if (t == 0) rs[64] = mb;
    }
    __syncthreads();

    // ---- interval, beta, coefficients, PS fold (deg 8, base 3, q<=2) ----
    const float lo = 0.95f;
    float bmax = sqrtf(rs[64] * 1.001f) + 5e-3f;
    bmax = fmaxf(bmax, lo + 0.5f);
    const float cc     = 0.5f * (bmax + lo);
    const float dd     = 0.5f * (bmax - lo);
    const float inv_dd = 1.0f / dd;
    const float inv_d2 = inv_dd * inv_dd;
    const float ratio  = cc * inv_dd;
    const float beta   = ratio - sqrtf(ratio * ratio - 1.0f);

    float a[9];
    a[0] = logf(dd / (2.0f * beta));
    {
        float p = beta;
        a[1] = 2.f * p;
        #pragma unroll
        for (int k = 2; k <= 8; k++) { p = -p * beta; a[k] = 2.f * p / (float)k; }
    }
    float cf[3][3];
    #pragma unroll
    for (int q = 0; q < 3; q++)
        #pragma unroll
        for (int r = 0; r < 3; r++) cf[q][r] = 0.f;
    #pragma unroll
    for (int k = 8; k >= 3; k--) {
        const int q = k / 3, r = k - 3 * q;
        if (r > 0) { cf[q][r] = 2.f * a[k]; a[3 * q - r] -= a[k]; }
        else       { cf[q][0] = a[k]; }
    }
    #pragma unroll
    for (int r = 0; r < 3; r++) cf[0][r] = a[r];
    const float g0 = cf[0][0] - cf[2][0];
    const float g1 = cf[0][1] - cf[2][1];
    const float g2 = cf[0][2] - cf[2][2];

    // ---- fused elementwise (in place): T2s = T2, Xs = X~ ----
    const float t2diag = 2.f * cc * cc * inv_d2 - 1.f;
    for (int e = t; e < MATSZ; e += NTHREADS) {
        const int r = e >> 6, j = e & 63;
        const int idx = r * LDM + j;
        const float x  = Xs[idx];
        const float x2 = T2s[idx];
        const float dl = (r == j) ? 1.f : 0.f;
        T2s[idx] = (2.f * x2 - 4.f * cc * x) * inv_d2 + t2diag * dl;
        Xs[idx]  = (x - cc * dl) * inv_dd;
    }
    __syncthreads();

    // ---- matmul 2: W = T3 = 2 X~ T2 - X~ ; then W->Xs, P2->T2s ;
    //      P1 tile cached in registers; E0 tile PRE-STORED to gmem output ----
    float p1t[8][4];
    float w[8][4], xt[8][4], t2[8][4];
    if (active) {
        float s[8][4];
        mm_tile8(Xs, T2s, i0, j0, s);
        load_tile8(Xs, i0, j0, xt);
        load_tile8(T2s, i0, j0, t2);
        #pragma unroll
        for (int r = 0; r < 8; r++)
            #pragma unroll
            for (int c = 0; c < 4; c++)
                w[r][c] = 2.f * s[r][c] - xt[r][c];
    }
    __syncthreads();   // ALL threads: matmul-2 reads of Xs/T2s complete
    if (active) {
        store_tile8_sym(Xs, i0, j0, straddle, w);          // W overwrites X~
        float p2t[8][4];
        #pragma unroll
        for (int r = 0; r < 8; r++)
            #pragma unroll
            for (int c = 0; c < 4; c++) {
                const float dl = ((i0 + r) == (j0 + c)) ? 1.f : 0.f;
                p2t[r][c] = cf[2][0] * dl + cf[2][1] * xt[r][c] + cf[2][2] * t2[r][c];
            }
        store_tile8_sym(T2s, i0, j0, straddle, p2t);       // P2 overwrites T2
        #pragma unroll
        for (int r = 0; r < 8; r++)
            #pragma unroll
            for (int c = 0; c < 4; c++) {
                const float dl = ((i0 + r) == (j0 + c)) ? 1.f : 0.f;
                p1t[r][c] = cf[1][0] * dl + cf[1][1] * xt[r][c] + cf[1][2] * t2[r][c];
                // E0 = P0 - P2: park in the output slot this thread owns;
                // read back (same thread, same address) at matmul 4.
                const int i = i0 + r, j = j0 + c;
                if (i <= j)
                    o[i * MATN - (i * (i - 1)) / 2 + (j - i)] =
                        g0 * dl + g1 * xt[r][c] + g2 * t2[r][c];
            }
    }
    __syncthreads();

    // ---- matmul 3: b1 = 2 W P2 + P1 -> T2s (P2 dead) ----
    float b1t[8][4];
    if (active) {
        float s[8][4];
        mm_tile8(Xs, T2s, i0, j0, s);
        #pragma unroll
        for (int r = 0; r < 8; r++)
            #pragma unroll
            for (int c = 0; c < 4; c++)
                b1t[r][c] = 2.f * s[r][c] + p1t[r][c];
    }
    __syncthreads();   // ALL threads: matmul-3 reads of T2s complete
    if (active)
        store_tile8_sym(T2s, i0, j0, straddle, b1t);
    __syncthreads();

    // ---- matmul 4: S = W b1 + E0(prefetched from out) -> output ----
    if (active) {
        // prefetch E0 (same-thread RAW on global; latency hidden by the matmul)
        float e0r[8][4];
        #pragma unroll
        for (int r = 0; r < 8; r++)
            #pragma unroll
            for (int c = 0; c < 4; c++) {
                const int i = i0 + r, j = j0 + c;
                if (i <= j)
                    e0r[r][c] = o[i * MATN - (i * (i - 1)) / 2 + (j - i)];
            }
        float s[8][4];
        mm_tile8(Xs, T2s, i0, j0, s);
        #pragma unroll
        for (int r = 0; r < 8; r++)
            #pragma unroll
            for (int c = 0; c < 4; c++) {
                const int i = i0 + r, j = j0 + c;
                if (i <= j)
                    o[i * MATN - (i * (i - 1)) / 2 + (j - i)] = s[r][c] + e0r[r][c];
            }
    }
}

extern "C" void kernel_launch(void* const* d_in, const int* in_sizes, int n_in,
                              void* d_out, int out_size)
{
    const float* x = (const float*)d_in[0];
    float* out = (float*)d_out;
    const int B = in_sizes[0] / MATSZ;

    const int smem_bytes = (2 * MATN * LDM + 132) * (int)sizeof(float);
    cudaFuncSetAttribute(spd_log_cheb_e0g_kernel,
                         cudaFuncAttributeMaxDynamicSharedMemorySize, smem_bytes);

    spd_log_cheb_e0g_kernel<<<B, NTHREADS, smem_bytes>>>(x, out);
}

// round 17
// speedup vs baseline: 1.0713x; 1.0713x over previous
#include <cuda_runtime.h>
#include <math.h>

// SPD log-map: Chebyshev deg-8 + Paterson-Stockmeyer, base W = T_3.
//   S = (P0 - P2) + W*(P1 + 2*W*P2),  P_q = cf[q][0] I + cf[q][1] X~ + cf[q][2] T2
// 4 matmuls: X*X (-> bound + T2 elementwise), W=T3, W*P2, W*b1.
// 8x4 register tiles over the upper triangle (72 tiles, 96 threads);
// A-operand rows read as contiguous float4 via symmetry (A[i][k]=A[k][i]).
// TWO smem matrix buffers, 5 CTAs/SM (128 regs, no spills).
// Inner product: packed fp32 FMA (fma.rn.f32x2), broadcast-B scheme
// (validated fastest). B load + bcasts issued FIRST (longest dep chain),
// unroll 8 for deeper load batching (load-use latency amortized over 2x FMA).
// Eigen bound: lammax <= sqrt(gersh(X^2)) (always valid, tighter here).

#define LDM      68
#define NTHREADS 96
#define NTILES   72
#define MATN     64
#define MATSZ    (MATN * MATN)
#define OUTSZ    2080

typedef unsigned long long u64;

__device__ __forceinline__ void fma2(u64& d, u64 a, u64 b) {
    asm("fma.rn.f32x2 %0, %1, %2, %0;" : "+l"(d) : "l"(a), "l"(b));
}
__device__ __forceinline__ u64 bcast2(float x) {
    u64 r; asm("mov.b64 %0, {%1, %1};" : "=l"(r) : "f"(x)); return r;
}

__device__ __forceinline__ void mm_tile8(const float* __restrict__ A,
                                         const float* __restrict__ B,
                                         int i0, int j0, float s[8][4])
{
    u64 acc[4][4];
    #pragma unroll
    for (int p = 0; p < 4; p++)
        #pragma unroll
        for (int c = 0; c < 4; c++) acc[p][c] = 0ull;
    const float* Ap = A + i0;
    const float* Bp = B + j0;
    #pragma unroll 8
    for (int kk = 0; kk < MATN; kk++) {
        // B first: it feeds the bcast MOVs (longest dependency chain)
        const float4 bv = *(const float4*)(Bp + kk * LDM);
        const u64 pb0 = bcast2(bv.x), pb1 = bcast2(bv.y);
        const u64 pb2 = bcast2(bv.z), pb3 = bcast2(bv.w);
        // A[i0..i0+7][kk] == A-row kk (symmetry) -> two 16B loads, pairs prepacked
        const ulonglong2 a0 = *(const ulonglong2*)(Ap + kk * LDM);      // rows (0,1),(2,3)
        const ulonglong2 a1 = *(const ulonglong2*)(Ap + kk * LDM + 4);  // rows (4,5),(6,7)
        const u64 pa[4] = {a0.x, a0.y, a1.x, a1.y};
        #pragma unroll
        for (int p = 0; p < 4; p++) {
            fma2(acc[p][0], pa[p], pb0);
            fma2(acc[p][1], pa[p], pb1);
            fma2(acc[p][2], pa[p], pb2);
            fma2(acc[p][3], pa[p], pb3);
        }
    }
    #pragma unroll
    for (int p = 0; p < 4; p++)
        #pragma unroll
        for (int c = 0; c < 4; c++) {
            float lo, hi;
            asm("mov.b64 {%0, %1}, %2;" : "=f"(lo), "=f"(hi) : "l"(acc[p][c]));
            s[2 * p][c] = lo;
            s[2 * p + 1][c] = hi;
        }
}

__device__ __forceinline__ void load_tile8(const float* __restrict__ M,
                                           int i0, int j0, float v[8][4])
{
    #pragma unroll
    for (int r = 0; r < 8; r++) {
        const float4 t = *(const float4*)(M + (i0 + r) * LDM + j0);
        v[r][0] = t.x; v[r][1] = t.y; v[r][2] = t.z; v[r][3] = t.w;
    }
}

__device__ __forceinline__ void store_tile8_sym(float* __restrict__ M,
                                                int i0, int j0, bool straddle,
                                                const float v[8][4])
{
    if (!straddle) {
        #pragma unroll
        for (int r = 0; r < 8; r++)
            *(float4*)(M + (i0 + r) * LDM + j0) =
                make_float4(v[r][0], v[r][1], v[r][2], v[r][3]);
        #pragma unroll
        for (int c = 0; c < 4; c++) {
            *(float4*)(M + (j0 + c) * LDM + i0) =
                make_float4(v[0][c], v[1][c], v[2][c], v[3][c]);
            *(float4*)(M + (j0 + c) * LDM + i0 + 4) =
                make_float4(v[4][c], v[5][c], v[6][c], v[7][c]);
        }
    } else {
        #pragma unroll
        for (int r = 0; r < 8; r++)
            #pragma unroll
            for (int c = 0; c < 4; c++) {
                const int i = i0 + r, j = j0 + c;
                if (i <= j) {
                    M[i * LDM + j] = v[r][c];
                    if (i < j) M[j * LDM + i] = v[r][c];
                }
            }
    }
}

__global__ void __launch_bounds__(NTHREADS, 5)
spd_log_cheb_u8_kernel(const float* __restrict__ xg, float* __restrict__ outg)
{
    extern __shared__ float sm[];
    float* Xs  = sm + 0 * MATN * LDM;   // X -> X~ -> W
    float* T2s = sm + 1 * MATN * LDM;   // X^2 -> T2 -> P2 -> b1
    float* rs  = sm + 2 * MATN * LDM;   // 64 rowsums + 1 max

    const int t = threadIdx.x;
    const float* X = xg + (size_t)blockIdx.x * MATSZ;

    // ---- load X ----
    for (int e = t; e < MATSZ; e += NTHREADS)
        Xs[(e >> 6) * LDM + (e & 63)] = X[e];
    __syncthreads();

    // ---- tile assignment: t < 72 owns 8x4 tile (bi, bj), bj >= 2*bi ----
    const bool active = (t < NTILES);
    int bi = 0, bj = 0;
    {
        int tt = active ? t : 0;
        while (tt >= 16 - 2 * bi) { tt -= 16 - 2 * bi; bi++; }
        bj = 2 * bi + tt;
    }
    const int i0 = bi * 8, j0 = bj * 4;
    const bool straddle = (bj <= 2 * bi + 1);

    // ---- matmul 1: X2 = X * X -> T2s ----
    if (active) {
        float s[8][4];
        mm_tile8(Xs, Xs, i0, j0, s);
        store_tile8_sym(T2s, i0, j0, straddle, s);
    }
    __syncthreads();

    // ---- Gershgorin bound on X^2 (lammax <= sqrt(gersh(X^2))) ----
    if (t < MATN) {
        float sb = 0.f;
        #pragma unroll
        for (int j = 0; j < MATN; j += 4) {
            const float4 xb = *(const float4*)(T2s + t * LDM + j);
            sb += fabsf(xb.x) + fabsf(xb.y) + fabsf(xb.z) + fabsf(xb.w);
        }
        rs[t] = sb;
    }
    __syncthreads();
    if (t < 32) {
        float mb = fmaxf(rs[t], rs[t + 32]);
        #pragma unroll
        for (int o = 16; o > 0; o >>= 1)
            mb = fmaxf(mb, __shfl_xor_sync(0xffffffffu, mb, o));
        if (t == 0) rs[64] = mb;
    }
    __syncthreads();

    // ---- interval, beta, coefficients, PS fold (deg 8, base 3, q<=2) ----
    const float lo = 0.95f;
    float bmax = sqrtf(rs[64] * 1.001f) + 5e-3f;
    bmax = fmaxf(bmax, lo + 0.5f);
    const float cc     = 0.5f * (bmax + lo);
    const float dd     = 0.5f * (bmax - lo);
    const float inv_dd = 1.0f / dd;
    const float inv_d2 = inv_dd * inv_dd;
    const float ratio  = cc * inv_dd;
    const float beta   = ratio - sqrtf(ratio * ratio - 1.0f);

    float a[9];
    a[0] = logf(dd / (2.0f * beta));
    {
        float p = beta;
        a[1] = 2.f * p;
        #pragma unroll
        for (int k = 2; k <= 8; k++) { p = -p * beta; a[k] = 2.f * p / (float)k; }
    }
    float cf[3][3];
    #pragma unroll
    for (int q = 0; q < 3; q++)
        #pragma unroll
        for (int r = 0; r < 3; r++) cf[q][r] = 0.f;
    #pragma unroll
    for (int k = 8; k >= 3; k--) {
        const int q = k / 3, r = k - 3 * q;
        if (r > 0) { cf[q][r] = 2.f * a[k]; a[3 * q - r] -= a[k]; }
        else       { cf[q][0] = a[k]; }
    }
    #pragma unroll
    for (int r = 0; r < 3; r++) cf[0][r] = a[r];
    const float g0 = cf[0][0] - cf[2][0];
    const float g1 = cf[0][1] - cf[2][1];
    const float g2 = cf[0][2] - cf[2][2];

    // ---- fused elementwise (in place): T2s = T2, Xs = X~ ----
    const float t2diag = 2.f * cc * cc * inv_d2 - 1.f;
    for (int e = t; e < MATSZ; e += NTHREADS) {
        const int r = e >> 6, j = e & 63;
        const int idx = r * LDM + j;
        const float x  = Xs[idx];
        const float x2 = T2s[idx];
        const float dl = (r == j) ? 1.f : 0.f;
        T2s[idx] = (2.f * x2 - 4.f * cc * x) * inv_d2 + t2diag * dl;
        Xs[idx]  = (x - cc * dl) * inv_dd;
    }
    __syncthreads();

    // ---- matmul 2: W = T3 = 2 X~ T2 - X~ ; then W->Xs, P2->T2s ;
    //      P1/E0 tiles cached in registers ----
    float p1t[8][4], e0t[8][4];
    float w[8][4], xt[8][4], t2[8][4];
    if (active) {
        float s[8][4];
        mm_tile8(Xs, T2s, i0, j0, s);
        load_tile8(Xs, i0, j0, xt);
        load_tile8(T2s, i0, j0, t2);
        #pragma unroll
        for (int r = 0; r < 8; r++)
            #pragma unroll
            for (int c = 0; c < 4; c++)
                w[r][c] = 2.f * s[r][c] - xt[r][c];
    }
    __syncthreads();   // ALL threads: matmul-2 reads of Xs/T2s complete
    if (active) {
        store_tile8_sym(Xs, i0, j0, straddle, w);          // W overwrites X~
        float p2t[8][4];
        #pragma unroll
        for (int r = 0; r < 8; r++)
            #pragma unroll
            for (int c = 0; c < 4; c++) {
                const float dl = ((i0 + r) == (j0 + c)) ? 1.f : 0.f;
                p2t[r][c] = cf[2][0] * dl + cf[2][1] * xt[r][c] + cf[2][2] * t2[r][c];
            }
        store_tile8_sym(T2s, i0, j0, straddle, p2t);       // P2 overwrites T2
        #pragma unroll
        for (int r = 0; r < 8; r++)
            #pragma unroll
            for (int c = 0; c < 4; c++) {
                const float dl = ((i0 + r) == (j0 + c)) ? 1.f : 0.f;
                p1t[r][c] = cf[1][0] * dl + cf[1][1] * xt[r][c] + cf[1][2] * t2[r][c];
                e0t[r][c] = g0 * dl + g1 * xt[r][c] + g2 * t2[r][c];
            }
    }
    __syncthreads();

    // ---- matmul 3: b1 = 2 W P2 + P1 -> T2s (P2 dead) ----
    float b1t[8][4];
    if (active) {
        float s[8][4];
        mm_tile8(Xs, T2s, i0, j0, s);
        #pragma unroll
        for (int r = 0; r < 8; r++)
            #pragma unroll
            for (int c = 0; c < 4; c++)
                b1t[r][c] = 2.f * s[r][c] + p1t[r][c];
    }
    __syncthreads();   // ALL threads: matmul-3 reads of T2s complete
    if (active)
        store_tile8_sym(T2s, i0, j0, straddle, b1t);
    __syncthreads();

    // ---- matmul 4: S = W b1 + (P0 - P2) -> output ----
    if (active) {
        float s[8][4];
        mm_tile8(Xs, T2s, i0, j0, s);
        float* o = outg + (size_t)blockIdx.x * OUTSZ;
        #pragma unroll
        for (int r = 0; r < 8; r++)
            #pragma unroll
            for (int c = 0; c < 4; c++) {
                const int i = i0 + r, j = j0 + c;
                if (i <= j)
                    o[i * MATN - (i * (i - 1)) / 2 + (j - i)] = s[r][c] + e0t[r][c];
            }
    }
}

extern "C" void kernel_launch(void* const* d_in, const int* in_sizes, int n_in,
                              void* d_out, int out_size)
{
    const float* x = (const float*)d_in[0];
    float* out = (float*)d_out;
    const int B = in_sizes[0] / MATSZ;

    const int smem_bytes = (2 * MATN * LDM + 132) * (int)sizeof(float);
    cudaFuncSetAttribute(spd_log_cheb_u8_kernel,
                         cudaFuncAttributeMaxDynamicSharedMemorySize, smem_bytes);

    spd_log_cheb_u8_kernel<<<B, NTHREADS, smem_bytes>>>(x, out);
}